// round 13
// baseline (speedup 1.0000x reference)
#include <cuda_runtime.h>
#include <cuda_bf16.h>
#include <cstdint>

// ---------------------------------------------------------------------------
// RowLSTM: x(16,64,64,64), Wi(512,64,1,3), bi(512), Wh(512,128), bh(512)
// out: (16,128,64,64) fp32
// Phase 1 (i2h): mma.sync bf16 3-pass hi/lo conv-GEMM; B-fragment words made
//   smem-adjacent via permuted cq layout -> LDS.64 per fragment.
// Phase 2 (rec): R11 winner (512 thr, register-resident Wh) + split hi/lo
//   accumulators (shorter HMMA dependency chains).
// ---------------------------------------------------------------------------

#define B_  16
#define C_  64
#define H_  64
#define W_  64
#define HID_ 128
#define G_  512
#define K_  192

static __device__ float    g_i2h[(size_t)H_ * B_ * W_ * G_];   // [h][b][w][g]
static __device__ uint32_t g_xTh[(size_t)B_ * H_ * 66 * 32];   // [b][h][wp][cq'] bf16x2 hi (permuted cq)
static __device__ uint32_t g_xTl[(size_t)B_ * H_ * 66 * 32];   // lo
static __device__ uint32_t g_WiFh[49152];                      // [kw][kt][mt][lane][reg]
static __device__ uint32_t g_WiFl[49152];
static __device__ uint32_t g_WhFh[32768];                      // [kt(8)][mt(32)][lane(32)][reg(4)]

__device__ __forceinline__ float sigmf(float v) {
    return __fdividef(1.0f, 1.0f + __expf(-v));
}
__device__ __forceinline__ float tanhf_(float v) {
    return __fdividef(2.0f, 1.0f + __expf(-2.0f * v)) - 1.0f;
}
__device__ __forceinline__ uint32_t pkbf(float a, float b) {
    __nv_bfloat162 t = __floats2bfloat162_rn(a, b);
    return *reinterpret_cast<uint32_t*>(&t);
}
__device__ __forceinline__ void split2(float v, float& hi, float& lo) {
    __nv_bfloat16 h = __float2bfloat16_rn(v);
    hi = __bfloat162float(h);
    lo = v - hi;
}
__device__ __forceinline__ void mma_bf16(float d[4], const uint32_t a[4], const uint32_t b[2]) {
    asm volatile(
        "mma.sync.aligned.m16n8k16.row.col.f32.bf16.bf16.f32 "
        "{%0,%1,%2,%3},{%4,%5,%6,%7},{%8,%9},{%0,%1,%2,%3};"
        : "+f"(d[0]), "+f"(d[1]), "+f"(d[2]), "+f"(d[3])
        : "r"(a[0]), "r"(a[1]), "r"(a[2]), "r"(a[3]), "r"(b[0]), "r"(b[1]));
}

// ---------------------------------------------------------------------------
// Prep 1: x -> xT hi/lo bf16x2, layout [b][h][wp(66)][cq'(32)], zero-padded ends.
// cq' permutation within each 8-group: lq<4 -> 2*lq ; else 2*(lq-4)+1, so a
// B-fragment's (k, k+8) word pair is contiguous 8 bytes in smem.
// ---------------------------------------------------------------------------
__global__ void __launch_bounds__(256)
prep_x(const float* __restrict__ x)
{
    const int b = blockIdx.x >> 6, h = blockIdx.x & 63;
    const int tid = threadIdx.x;
    __shared__ float xt[64][65];
    for (int idx = tid; idx < 4096; idx += 256) {
        int c = idx >> 6, w = idx & 63;
        xt[c][w] = x[(((size_t)b * C_ + c) * H_ + h) * W_ + w];
    }
    __syncthreads();
    for (int idx = tid; idx < 66 * 32; idx += 256) {
        int wp = idx >> 5, cq = idx & 31, c0 = cq * 2;
        uint32_t vh = 0u, vl = 0u;
        if (wp >= 1 && wp <= 64) {
            int w = wp - 1;
            float ah, al, bh, bl;
            split2(xt[c0][w], ah, al);
            split2(xt[c0 + 1][w], bh, bl);
            vh = pkbf(ah, bh);
            vl = pkbf(al, bl);
        }
        // permuted destination position within the kt-group of 8
        int kt = cq >> 3, lq = cq & 7;
        int pos = (lq < 4) ? (2 * lq) : (2 * (lq - 4) + 1);
        int cqp = kt * 8 + pos;
        size_t o = (((size_t)b * H_ + h) * 66 + wp) * 32 + cqp;
        g_xTh[o] = vh;
        g_xTl[o] = vl;
    }
}

// ---------------------------------------------------------------------------
// Prep 2: Wi -> fragment-linear hi/lo [kw(3)][kt(4)][mt(32)][lane(32)][reg(4)]
// ---------------------------------------------------------------------------
__global__ void __launch_bounds__(512)
prep_wif(const float* __restrict__ Wi)
{
    int gid = blockIdx.x * 512 + threadIdx.x;   // < 49152
    int reg = gid & 3, lane = (gid >> 2) & 31, mt = (gid >> 7) & 31;
    int kt = (gid >> 12) & 3, kw = gid >> 14;
    int grp = lane >> 2, tig = lane & 3;
    int g  = mt * 16 + grp + 8 * (reg & 1);
    int c0 = kt * 16 + 2 * tig + 8 * (reg >> 1);
    float a = Wi[(size_t)g * K_ + c0 * 3 + kw];
    float b = Wi[(size_t)g * K_ + (c0 + 1) * 3 + kw];
    float ah, al, bh, bl;
    split2(a, ah, al);
    split2(b, bh, bl);
    g_WiFh[gid] = pkbf(ah, bh);
    g_WiFl[gid] = pkbf(al, bl);
}

// ---------------------------------------------------------------------------
// Prep 3: Wh -> fragment-linear hi only [kt(8)][mt(32)][lane(32)][reg(4)]
// ---------------------------------------------------------------------------
__global__ void __launch_bounds__(512)
prep_whf(const float* __restrict__ Wh)
{
    int gid = blockIdx.x * 512 + threadIdx.x;   // < 32768
    int reg = gid & 3, lane = (gid >> 2) & 31, mt = (gid >> 7) & 31;
    int kt = gid >> 12;
    int grp = lane >> 2, tig = lane & 3;
    int g = mt * 16 + grp + 8 * (reg & 1);
    int k = kt * 16 + 2 * tig + 8 * (reg >> 1);
    float a = Wh[(size_t)g * HID_ + k];
    float b = Wh[(size_t)g * HID_ + k + 1];
    g_WhFh[gid] = pkbf(__bfloat162float(__float2bfloat16_rn(a)),
                       __bfloat162float(__float2bfloat16_rn(b)));
}

// ---------------------------------------------------------------------------
// Kernel A: i2h. Grid 512 = gc(8) x b(16) x ic(4). 256 threads = 8 warps.
// B fragments now one LDS.64 each (permuted layout).
// ---------------------------------------------------------------------------
#define A_HI  0
#define A_LO  24576
#define XS_HI 49152
#define XS_LO 68160
#define STGB  49152
#define SMEM_I2H 87168

__global__ void __launch_bounds__(256, 2)
i2h_kernel()
{
    extern __shared__ char sm[];
    const int gc = blockIdx.x & 7;
    const int b  = (blockIdx.x >> 3) & 15;
    const int ic = blockIdx.x >> 7;
    const int tid  = threadIdx.x;
    const int lane = tid & 31;
    const int warp = tid >> 5;
    const int wg   = warp >> 2;
    const int wn   = warp & 3;
    const int grp  = lane >> 2;
    const int tig  = lane & 3;

    uint4* ah4 = reinterpret_cast<uint4*>(sm + A_HI);
    uint4* al4 = reinterpret_cast<uint4*>(sm + A_LO);
    const uint4* wfh4 = reinterpret_cast<const uint4*>(g_WiFh);
    const uint4* wfl4 = reinterpret_cast<const uint4*>(g_WiFl);

    for (int idx = tid; idx < 1536; idx += 256) {
        int ln = idx & 31, gt = (idx >> 5) & 3, kt = (idx >> 7) & 3, kw = idx >> 9;
        int src = ((kw * 4 + kt) * 32 + gc * 4 + gt) * 32 + ln;
        int dst = ((kw * 4 + kt) * 4 + gt) * 32 + ln;
        ah4[dst] = wfh4[src];
        al4[dst] = wfl4[src];
    }

    int nbase[4];
#pragma unroll
    for (int nt2 = 0; nt2 < 4; nt2++) {
        int n = (wn * 4 + nt2) * 8 + grp;
        int hs = n >> 6, w = n & 63;
        nbase[nt2] = hs * 9504 + w * 144;
    }

    uint32_t* xh = reinterpret_cast<uint32_t*>(sm + XS_HI);
    uint32_t* xl = reinterpret_cast<uint32_t*>(sm + XS_LO);
    float* stg = reinterpret_cast<float*>(sm + STGB);

    for (int i = 0; i < 8; i++) {
        const int it = ic * 8 + i;
        const int h0 = it * 2;
        __syncthreads();

        for (int idx = tid; idx < 2 * 66 * 32; idx += 256) {
            int hs = idx >> 11;
            int rem = idx - hs * 2112;
            int wp = rem >> 5, cq = rem & 31;
            size_t g = (((size_t)b * H_ + h0 + hs) * 66 + wp) * 32 + cq;
            int d = hs * 2376 + wp * 36 + cq;
            xh[d] = g_xTh[g];
            xl[d] = g_xTl[g];
        }
        __syncthreads();

        float d[2][4][4];
#pragma unroll
        for (int a = 0; a < 2; a++)
#pragma unroll
            for (int c = 0; c < 4; c++)
#pragma unroll
                for (int r = 0; r < 4; r++) d[a][c][r] = 0.f;

#pragma unroll
        for (int kk = 0; kk < 12; kk++) {
            const int kw = kk >> 2, kt = kk & 3;
            const int koff = kw * 144 + kt * 32 + tig * 8;   // permuted: pair contiguous

            uint4 ahf[2], alf[2];
#pragma unroll
            for (int gt2 = 0; gt2 < 2; gt2++) {
                int fo = (kk * 4 + wg * 2 + gt2) * 32 + lane;
                ahf[gt2] = ah4[fo];
                alf[gt2] = al4[fo];
            }
            uint2 bhf[4], blf[4];
#pragma unroll
            for (int nt2 = 0; nt2 < 4; nt2++) {
                int off = nbase[nt2] + koff;
                bhf[nt2] = *reinterpret_cast<const uint2*>(sm + XS_HI + off);
                blf[nt2] = *reinterpret_cast<const uint2*>(sm + XS_LO + off);
            }
#pragma unroll
            for (int gt2 = 0; gt2 < 2; gt2++)
#pragma unroll
                for (int nt2 = 0; nt2 < 4; nt2++)
                    mma_bf16(d[gt2][nt2], &ahf[gt2].x, &bhf[nt2].x);
#pragma unroll
            for (int gt2 = 0; gt2 < 2; gt2++)
#pragma unroll
                for (int nt2 = 0; nt2 < 4; nt2++)
                    mma_bf16(d[gt2][nt2], &ahf[gt2].x, &blf[nt2].x);
#pragma unroll
            for (int gt2 = 0; gt2 < 2; gt2++)
#pragma unroll
                for (int nt2 = 0; nt2 < 4; nt2++)
                    mma_bf16(d[gt2][nt2], &alf[gt2].x, &bhf[nt2].x);
        }
        __syncthreads();

#pragma unroll
        for (int gt2 = 0; gt2 < 2; gt2++) {
            int g0 = (wg * 2 + gt2) * 16 + grp;
#pragma unroll
            for (int nt2 = 0; nt2 < 4; nt2++) {
                int n0 = (wn * 4 + nt2) * 8 + 2 * tig;
                stg[n0 * 64 + g0]           = d[gt2][nt2][0];
                stg[(n0 + 1) * 64 + g0]     = d[gt2][nt2][1];
                stg[n0 * 64 + g0 + 8]       = d[gt2][nt2][2];
                stg[(n0 + 1) * 64 + g0 + 8] = d[gt2][nt2][3];
            }
        }
        __syncthreads();

#pragma unroll
        for (int u = 0; u < 8; u++) {
            int idx = tid + u * 256;
            int n = idx >> 4;
            int q4 = idx & 15;
            float4 v = *reinterpret_cast<const float4*>(&stg[n * 64 + q4 * 4]);
            size_t dst = ((size_t)(h0 + (n >> 6)) * B_ + b) * (W_ * G_)
                       + (size_t)(n & 63) * G_ + gc * 64 + q4 * 4;
            *reinterpret_cast<float4*>(&g_i2h[dst]) = v;
        }
    }
}

// ---------------------------------------------------------------------------
// Kernel B: recurrent scan (R11 winner) + split hi/lo accumulators.
// 128 blocks = (b, w8), 512 threads; Wh fragments register-resident.
// ---------------------------------------------------------------------------
#define GBS 516
#define HBS 136
#define HP  10

__global__ void __launch_bounds__(512, 1)
rec_kernel(const float* __restrict__ bi, const float* __restrict__ bh,
           float* __restrict__ out)
{
    const int b  = blockIdx.x >> 3;
    const int w0 = (blockIdx.x & 7) * 8;
    const int t  = threadIdx.x;
    const int lane = t & 31;
    const int warp = t >> 5;        // 0..15
    const int grp  = lane >> 2;
    const int tig  = lane & 3;

    __shared__ __nv_bfloat16 hbh[8 * HBS];
    __shared__ __nv_bfloat16 hbl[8 * HBS];
    __shared__ float hfp[HID_ * HP];
    __shared__ float gbuf[8 * GBS];

    for (int p = t; p < 8 * HBS; p += 512) {
        hbh[p] = __float2bfloat16(0.f);
        hbl[p] = __float2bfloat16(0.f);
    }
    __syncthreads();

    float bias_i[2], bias_f[2], bias_o[2], bias_g[2];
#pragma unroll
    for (int pp = 0; pp < 2; pp++) {
        int d = (t + pp * 512) & 127;
        bias_i[pp] = bi[d] + bh[d];
        bias_f[pp] = bi[HID_ + d] + bh[HID_ + d];
        bias_o[pp] = bi[2 * HID_ + d] + bh[2 * HID_ + d];
        bias_g[pp] = bi[3 * HID_ + d] + bh[3 * HID_ + d];
    }
    float creg[2] = {0.f, 0.f};

    const uint4* whfh = reinterpret_cast<const uint4*>(g_WhFh);
    const int mt0 = warp * 2;
    uint4 whr[16];
#pragma unroll
    for (int kt = 0; kt < 8; kt++) {
        whr[2 * kt]     = whfh[(kt * 32 + mt0) * 32 + lane];
        whr[2 * kt + 1] = whfh[(kt * 32 + mt0 + 1) * 32 + lane];
    }

    const int bofs = grp * (HBS * 2) + tig * 4;

    int pcol[2], pd[2];
#pragma unroll
    for (int pp = 0; pp < 2; pp++) {
        int p = t + pp * 512;
        pcol[pp] = p >> 7;
        pd[pp]   = p & 127;
    }

    for (int row = 0; row < H_; row++) {
        float ivr[2][4];
#pragma unroll
        for (int pp = 0; pp < 2; pp++) {
            const float* iv = &g_i2h[((((size_t)row * B_ + b) * W_) + w0 + pcol[pp]) * G_ + pd[pp]];
            ivr[pp][0] = __ldg(iv);
            ivr[pp][1] = __ldg(iv + HID_);
            ivr[pp][2] = __ldg(iv + 2 * HID_);
            ivr[pp][3] = __ldg(iv + 3 * HID_);
        }

        // split accumulators: hi-pass and lo-pass independent chains
        float d0h[4] = {0.f, 0.f, 0.f, 0.f}, d0l[4] = {0.f, 0.f, 0.f, 0.f};
        float d1h[4] = {0.f, 0.f, 0.f, 0.f}, d1l[4] = {0.f, 0.f, 0.f, 0.f};
#pragma unroll
        for (int kt = 0; kt < 8; kt++) {
            uint32_t bhf[2], blf[2];
            const char* ph = reinterpret_cast<const char*>(hbh) + bofs + kt * 32;
            const char* pl = reinterpret_cast<const char*>(hbl) + bofs + kt * 32;
            bhf[0] = *reinterpret_cast<const uint32_t*>(ph);
            bhf[1] = *reinterpret_cast<const uint32_t*>(ph + 16);
            blf[0] = *reinterpret_cast<const uint32_t*>(pl);
            blf[1] = *reinterpret_cast<const uint32_t*>(pl + 16);
            mma_bf16(d0h, &whr[2 * kt].x, bhf);
            mma_bf16(d1h, &whr[2 * kt + 1].x, bhf);
            mma_bf16(d0l, &whr[2 * kt].x, blf);
            mma_bf16(d1l, &whr[2 * kt + 1].x, blf);
        }

        {
            int g0 = mt0 * 16 + grp;
            gbuf[(2 * tig) * GBS + g0]          = d0h[0] + d0l[0];
            gbuf[(2 * tig + 1) * GBS + g0]      = d0h[1] + d0l[1];
            gbuf[(2 * tig) * GBS + g0 + 8]      = d0h[2] + d0l[2];
            gbuf[(2 * tig + 1) * GBS + g0 + 8]  = d0h[3] + d0l[3];
            int g1 = g0 + 16;
            gbuf[(2 * tig) * GBS + g1]          = d1h[0] + d1l[0];
            gbuf[(2 * tig + 1) * GBS + g1]      = d1h[1] + d1l[1];
            gbuf[(2 * tig) * GBS + g1 + 8]      = d1h[2] + d1l[2];
            gbuf[(2 * tig + 1) * GBS + g1 + 8]  = d1h[3] + d1l[3];
        }
        __syncthreads();

#pragma unroll
        for (int pp = 0; pp < 2; pp++) {
            int col = pcol[pp];
            int d   = pd[pp];
            const float* gb = &gbuf[col * GBS];
            float ig = gb[d]            + ivr[pp][0] + bias_i[pp];
            float fg = gb[HID_ + d]     + ivr[pp][1] + bias_f[pp];
            float og = gb[2 * HID_ + d] + ivr[pp][2] + bias_o[pp];
            float gg = gb[3 * HID_ + d] + ivr[pp][3] + bias_g[pp];
            float cv = sigmf(fg) * creg[pp] + sigmf(ig) * tanhf_(gg);
            float hv = sigmf(og) * tanhf_(cv);
            creg[pp] = cv;
            hfp[d * HP + col] = hv;
            float hh, hl;
            split2(hv, hh, hl);
            hbh[col * HBS + d] = __float2bfloat16(hh);
            hbl[col * HBS + d] = __float2bfloat16(hl);
        }
        __syncthreads();

        if (t < HID_) {
            const int d = t;
            float4 v0 = make_float4(hfp[d * HP + 0], hfp[d * HP + 1],
                                    hfp[d * HP + 2], hfp[d * HP + 3]);
            float4 v1 = make_float4(hfp[d * HP + 4], hfp[d * HP + 5],
                                    hfp[d * HP + 6], hfp[d * HP + 7]);
            float* op = out + ((((size_t)b * HID_ + d) * H_) + row) * W_ + w0;
            *reinterpret_cast<float4*>(op)     = v0;
            *reinterpret_cast<float4*>(op + 4) = v1;
        }
        __syncthreads();
    }
}

// ---------------------------------------------------------------------------
extern "C" void kernel_launch(void* const* d_in, const int* in_sizes, int n_in,
                              void* d_out, int out_size)
{
    (void)in_sizes; (void)n_in; (void)out_size;
    const float* x  = (const float*)d_in[0];
    const float* Wi = (const float*)d_in[1];
    const float* bi = (const float*)d_in[2];
    const float* Wh = (const float*)d_in[3];
    const float* bh = (const float*)d_in[4];
    float* out = (float*)d_out;

    static bool attr_set = false;
    if (!attr_set) {
        cudaFuncSetAttribute(i2h_kernel, cudaFuncAttributeMaxDynamicSharedMemorySize, SMEM_I2H);
        attr_set = true;
    }

    prep_x<<<B_ * H_, 256>>>(x);
    prep_wif<<<96, 512>>>(Wi);
    prep_whf<<<64, 512>>>(Wh);
    i2h_kernel<<<512, 256, SMEM_I2H>>>();
    rec_kernel<<<B_ * (W_ / 8), 512>>>(bi, bh, out);
}

// round 14
// speedup vs baseline: 1.1275x; 1.1275x over previous
#include <cuda_runtime.h>
#include <cuda_bf16.h>
#include <cstdint>

// ---------------------------------------------------------------------------
// RowLSTM: x(16,64,64,64), Wi(512,64,1,3), bi(512), Wh(512,128), bh(512)
// out: (16,128,64,64) fp32
// Phase 1 (i2h): mma.sync bf16 3-pass hi/lo conv-GEMM (R8/R11 proven form)
// Phase 2 (rec): R11 winner (512 thr, register-resident Wh) with HW
//   tanh.approx pointwise (sigmoid = 0.5*tanh(0.5v)+0.5).
// ---------------------------------------------------------------------------

#define B_  16
#define C_  64
#define H_  64
#define W_  64
#define HID_ 128
#define G_  512
#define K_  192

static __device__ float    g_i2h[(size_t)H_ * B_ * W_ * G_];   // [h][b][w][g]
static __device__ uint32_t g_xTh[(size_t)B_ * H_ * 66 * 32];   // [b][h][wp][cq] bf16x2 hi
static __device__ uint32_t g_xTl[(size_t)B_ * H_ * 66 * 32];   // lo
static __device__ uint32_t g_WiFh[49152];                      // [kw][kt][mt][lane][reg]
static __device__ uint32_t g_WiFl[49152];
static __device__ uint32_t g_WhFh[32768];                      // [kt(8)][mt(32)][lane(32)][reg(4)]

__device__ __forceinline__ float tanh_hw(float v) {
    float r; asm("tanh.approx.f32 %0, %1;" : "=f"(r) : "f"(v)); return r;
}
__device__ __forceinline__ float sigm_hw(float v) {
    return fmaf(tanh_hw(0.5f * v), 0.5f, 0.5f);
}
__device__ __forceinline__ uint32_t pkbf(float a, float b) {
    __nv_bfloat162 t = __floats2bfloat162_rn(a, b);
    return *reinterpret_cast<uint32_t*>(&t);
}
__device__ __forceinline__ void split2(float v, float& hi, float& lo) {
    __nv_bfloat16 h = __float2bfloat16_rn(v);
    hi = __bfloat162float(h);
    lo = v - hi;
}
__device__ __forceinline__ void mma_bf16(float d[4], const uint32_t a[4], const uint32_t b[2]) {
    asm volatile(
        "mma.sync.aligned.m16n8k16.row.col.f32.bf16.bf16.f32 "
        "{%0,%1,%2,%3},{%4,%5,%6,%7},{%8,%9},{%0,%1,%2,%3};"
        : "+f"(d[0]), "+f"(d[1]), "+f"(d[2]), "+f"(d[3])
        : "r"(a[0]), "r"(a[1]), "r"(a[2]), "r"(a[3]), "r"(b[0]), "r"(b[1]));
}

// ---------------------------------------------------------------------------
// Prep 1: x -> xT hi/lo bf16x2, layout [b][h][wp(66)][cq(32)], zero-padded ends
// ---------------------------------------------------------------------------
__global__ void __launch_bounds__(256)
prep_x(const float* __restrict__ x)
{
    const int b = blockIdx.x >> 6, h = blockIdx.x & 63;
    const int tid = threadIdx.x;
    __shared__ float xt[64][65];
    for (int idx = tid; idx < 4096; idx += 256) {
        int c = idx >> 6, w = idx & 63;
        xt[c][w] = x[(((size_t)b * C_ + c) * H_ + h) * W_ + w];
    }
    __syncthreads();
    for (int idx = tid; idx < 66 * 32; idx += 256) {
        int wp = idx >> 5, cq = idx & 31, c0 = cq * 2;
        uint32_t vh = 0u, vl = 0u;
        if (wp >= 1 && wp <= 64) {
            int w = wp - 1;
            float ah, al, bh, bl;
            split2(xt[c0][w], ah, al);
            split2(xt[c0 + 1][w], bh, bl);
            vh = pkbf(ah, bh);
            vl = pkbf(al, bl);
        }
        size_t o = (((size_t)b * H_ + h) * 66 + wp) * 32 + cq;
        g_xTh[o] = vh;
        g_xTl[o] = vl;
    }
}

// ---------------------------------------------------------------------------
// Prep 2 (merged): Wi -> fragment-linear hi/lo (blocks 0..95),
//                  Wh -> fragment-linear hi    (blocks 96..159)
// ---------------------------------------------------------------------------
__global__ void __launch_bounds__(512)
prep_w(const float* __restrict__ Wi, const float* __restrict__ Wh)
{
    if (blockIdx.x < 96) {
        int gid = blockIdx.x * 512 + threadIdx.x;   // < 49152
        int reg = gid & 3, lane = (gid >> 2) & 31, mt = (gid >> 7) & 31;
        int kt = (gid >> 12) & 3, kw = gid >> 14;
        int grp = lane >> 2, tig = lane & 3;
        int g  = mt * 16 + grp + 8 * (reg & 1);
        int c0 = kt * 16 + 2 * tig + 8 * (reg >> 1);
        float a = Wi[(size_t)g * K_ + c0 * 3 + kw];
        float b = Wi[(size_t)g * K_ + (c0 + 1) * 3 + kw];
        float ah, al, bh, bl;
        split2(a, ah, al);
        split2(b, bh, bl);
        g_WiFh[gid] = pkbf(ah, bh);
        g_WiFl[gid] = pkbf(al, bl);
    } else {
        int gid = (blockIdx.x - 96) * 512 + threadIdx.x;   // < 32768
        int reg = gid & 3, lane = (gid >> 2) & 31, mt = (gid >> 7) & 31;
        int kt = gid >> 12;
        int grp = lane >> 2, tig = lane & 3;
        int g = mt * 16 + grp + 8 * (reg & 1);
        int k = kt * 16 + 2 * tig + 8 * (reg >> 1);
        float a = Wh[(size_t)g * HID_ + k];
        float b = Wh[(size_t)g * HID_ + k + 1];
        g_WhFh[gid] = pkbf(__bfloat162float(__float2bfloat16_rn(a)),
                           __bfloat162float(__float2bfloat16_rn(b)));
    }
}

// ---------------------------------------------------------------------------
// Kernel A: i2h (R8/R11 winner, unchanged). Grid 512 = gc(8) x b(16) x ic(4).
// ---------------------------------------------------------------------------
#define A_HI  0
#define A_LO  24576
#define XS_HI 49152
#define XS_LO 68160
#define STGB  49152
#define SMEM_I2H 87168

__global__ void __launch_bounds__(256, 2)
i2h_kernel()
{
    extern __shared__ char sm[];
    const int gc = blockIdx.x & 7;
    const int b  = (blockIdx.x >> 3) & 15;
    const int ic = blockIdx.x >> 7;
    const int tid  = threadIdx.x;
    const int lane = tid & 31;
    const int warp = tid >> 5;
    const int wg   = warp >> 2;
    const int wn   = warp & 3;
    const int grp  = lane >> 2;
    const int tig  = lane & 3;

    uint4* ah4 = reinterpret_cast<uint4*>(sm + A_HI);
    uint4* al4 = reinterpret_cast<uint4*>(sm + A_LO);
    const uint4* wfh4 = reinterpret_cast<const uint4*>(g_WiFh);
    const uint4* wfl4 = reinterpret_cast<const uint4*>(g_WiFl);

    for (int idx = tid; idx < 1536; idx += 256) {
        int ln = idx & 31, gt = (idx >> 5) & 3, kt = (idx >> 7) & 3, kw = idx >> 9;
        int src = ((kw * 4 + kt) * 32 + gc * 4 + gt) * 32 + ln;
        int dst = ((kw * 4 + kt) * 4 + gt) * 32 + ln;
        ah4[dst] = wfh4[src];
        al4[dst] = wfl4[src];
    }

    int nbase[4];
#pragma unroll
    for (int nt2 = 0; nt2 < 4; nt2++) {
        int n = (wn * 4 + nt2) * 8 + grp;
        int hs = n >> 6, w = n & 63;
        nbase[nt2] = hs * 9504 + w * 144;
    }

    uint32_t* xh = reinterpret_cast<uint32_t*>(sm + XS_HI);
    uint32_t* xl = reinterpret_cast<uint32_t*>(sm + XS_LO);
    float* stg = reinterpret_cast<float*>(sm + STGB);

    for (int i = 0; i < 8; i++) {
        const int it = ic * 8 + i;
        const int h0 = it * 2;
        __syncthreads();

        for (int idx = tid; idx < 2 * 66 * 32; idx += 256) {
            int hs = idx >> 11;
            int rem = idx - hs * 2112;
            int wp = rem >> 5, cq = rem & 31;
            size_t g = (((size_t)b * H_ + h0 + hs) * 66 + wp) * 32 + cq;
            int d = hs * 2376 + wp * 36 + cq;
            xh[d] = g_xTh[g];
            xl[d] = g_xTl[g];
        }
        __syncthreads();

        float d[2][4][4];
#pragma unroll
        for (int a = 0; a < 2; a++)
#pragma unroll
            for (int c = 0; c < 4; c++)
#pragma unroll
                for (int r = 0; r < 4; r++) d[a][c][r] = 0.f;

#pragma unroll
        for (int kk = 0; kk < 12; kk++) {
            const int kw = kk >> 2, kt = kk & 3;
            const int koff = kw * 144 + kt * 32 + tig * 4;

            uint4 ahf[2], alf[2];
#pragma unroll
            for (int gt2 = 0; gt2 < 2; gt2++) {
                int fo = (kk * 4 + wg * 2 + gt2) * 32 + lane;
                ahf[gt2] = ah4[fo];
                alf[gt2] = al4[fo];
            }
            uint32_t bhf[4][2], blf[4][2];
#pragma unroll
            for (int nt2 = 0; nt2 < 4; nt2++) {
                int off = nbase[nt2] + koff;
                bhf[nt2][0] = *reinterpret_cast<const uint32_t*>(sm + XS_HI + off);
                bhf[nt2][1] = *reinterpret_cast<const uint32_t*>(sm + XS_HI + off + 16);
                blf[nt2][0] = *reinterpret_cast<const uint32_t*>(sm + XS_LO + off);
                blf[nt2][1] = *reinterpret_cast<const uint32_t*>(sm + XS_LO + off + 16);
            }
#pragma unroll
            for (int gt2 = 0; gt2 < 2; gt2++)
#pragma unroll
                for (int nt2 = 0; nt2 < 4; nt2++)
                    mma_bf16(d[gt2][nt2], &ahf[gt2].x, bhf[nt2]);
#pragma unroll
            for (int gt2 = 0; gt2 < 2; gt2++)
#pragma unroll
                for (int nt2 = 0; nt2 < 4; nt2++)
                    mma_bf16(d[gt2][nt2], &ahf[gt2].x, blf[nt2]);
#pragma unroll
            for (int gt2 = 0; gt2 < 2; gt2++)
#pragma unroll
                for (int nt2 = 0; nt2 < 4; nt2++)
                    mma_bf16(d[gt2][nt2], &alf[gt2].x, bhf[nt2]);
        }
        __syncthreads();

#pragma unroll
        for (int gt2 = 0; gt2 < 2; gt2++) {
            int g0 = (wg * 2 + gt2) * 16 + grp;
#pragma unroll
            for (int nt2 = 0; nt2 < 4; nt2++) {
                int n0 = (wn * 4 + nt2) * 8 + 2 * tig;
                stg[n0 * 64 + g0]           = d[gt2][nt2][0];
                stg[(n0 + 1) * 64 + g0]     = d[gt2][nt2][1];
                stg[n0 * 64 + g0 + 8]       = d[gt2][nt2][2];
                stg[(n0 + 1) * 64 + g0 + 8] = d[gt2][nt2][3];
            }
        }
        __syncthreads();

#pragma unroll
        for (int u = 0; u < 8; u++) {
            int idx = tid + u * 256;
            int n = idx >> 4;
            int q4 = idx & 15;
            float4 v = *reinterpret_cast<const float4*>(&stg[n * 64 + q4 * 4]);
            size_t dst = ((size_t)(h0 + (n >> 6)) * B_ + b) * (W_ * G_)
                       + (size_t)(n & 63) * G_ + gc * 64 + q4 * 4;
            *reinterpret_cast<float4*>(&g_i2h[dst]) = v;
        }
    }
}

// ---------------------------------------------------------------------------
// Kernel B: recurrent scan (R11 winner) with tanh.approx pointwise.
// 128 blocks = (b, w8), 512 threads; Wh fragments register-resident.
// ---------------------------------------------------------------------------
#define GBS 516
#define HBS 136
#define HP  10

__global__ void __launch_bounds__(512, 1)
rec_kernel(const float* __restrict__ bi, const float* __restrict__ bh,
           float* __restrict__ out)
{
    const int b  = blockIdx.x >> 3;
    const int w0 = (blockIdx.x & 7) * 8;
    const int t  = threadIdx.x;
    const int lane = t & 31;
    const int warp = t >> 5;        // 0..15
    const int grp  = lane >> 2;
    const int tig  = lane & 3;

    __shared__ __nv_bfloat16 hbh[8 * HBS];
    __shared__ __nv_bfloat16 hbl[8 * HBS];
    __shared__ float hfp[HID_ * HP];
    __shared__ float gbuf[8 * GBS];

    for (int p = t; p < 8 * HBS; p += 512) {
        hbh[p] = __float2bfloat16(0.f);
        hbl[p] = __float2bfloat16(0.f);
    }
    __syncthreads();

    float bias_i[2], bias_f[2], bias_o[2], bias_g[2];
#pragma unroll
    for (int pp = 0; pp < 2; pp++) {
        int d = (t + pp * 512) & 127;
        bias_i[pp] = bi[d] + bh[d];
        bias_f[pp] = bi[HID_ + d] + bh[HID_ + d];
        bias_o[pp] = bi[2 * HID_ + d] + bh[2 * HID_ + d];
        bias_g[pp] = bi[3 * HID_ + d] + bh[3 * HID_ + d];
    }
    float creg[2] = {0.f, 0.f};

    const uint4* whfh = reinterpret_cast<const uint4*>(g_WhFh);
    const int mt0 = warp * 2;
    uint4 whr[16];
#pragma unroll
    for (int kt = 0; kt < 8; kt++) {
        whr[2 * kt]     = whfh[(kt * 32 + mt0) * 32 + lane];
        whr[2 * kt + 1] = whfh[(kt * 32 + mt0 + 1) * 32 + lane];
    }

    const int bofs = grp * (HBS * 2) + tig * 4;

    int pcol[2], pd[2];
#pragma unroll
    for (int pp = 0; pp < 2; pp++) {
        int p = t + pp * 512;
        pcol[pp] = p >> 7;
        pd[pp]   = p & 127;
    }

    for (int row = 0; row < H_; row++) {
        float ivr[2][4];
#pragma unroll
        for (int pp = 0; pp < 2; pp++) {
            const float* iv = &g_i2h[((((size_t)row * B_ + b) * W_) + w0 + pcol[pp]) * G_ + pd[pp]];
            ivr[pp][0] = __ldg(iv);
            ivr[pp][1] = __ldg(iv + HID_);
            ivr[pp][2] = __ldg(iv + 2 * HID_);
            ivr[pp][3] = __ldg(iv + 3 * HID_);
        }

        float d0[4] = {0.f, 0.f, 0.f, 0.f};
        float d1[4] = {0.f, 0.f, 0.f, 0.f};
#pragma unroll
        for (int kt = 0; kt < 8; kt++) {
            uint32_t bhf[2], blf[2];
            const char* ph = reinterpret_cast<const char*>(hbh) + bofs + kt * 32;
            const char* pl = reinterpret_cast<const char*>(hbl) + bofs + kt * 32;
            bhf[0] = *reinterpret_cast<const uint32_t*>(ph);
            bhf[1] = *reinterpret_cast<const uint32_t*>(ph + 16);
            blf[0] = *reinterpret_cast<const uint32_t*>(pl);
            blf[1] = *reinterpret_cast<const uint32_t*>(pl + 16);
            mma_bf16(d0, &whr[2 * kt].x, bhf);
            mma_bf16(d1, &whr[2 * kt + 1].x, bhf);
            mma_bf16(d0, &whr[2 * kt].x, blf);
            mma_bf16(d1, &whr[2 * kt + 1].x, blf);
        }

        {
            int g0 = mt0 * 16 + grp;
            gbuf[(2 * tig) * GBS + g0]          = d0[0];
            gbuf[(2 * tig + 1) * GBS + g0]      = d0[1];
            gbuf[(2 * tig) * GBS + g0 + 8]      = d0[2];
            gbuf[(2 * tig + 1) * GBS + g0 + 8]  = d0[3];
            int g1 = g0 + 16;
            gbuf[(2 * tig) * GBS + g1]          = d1[0];
            gbuf[(2 * tig + 1) * GBS + g1]      = d1[1];
            gbuf[(2 * tig) * GBS + g1 + 8]      = d1[2];
            gbuf[(2 * tig + 1) * GBS + g1 + 8]  = d1[3];
        }
        __syncthreads();

#pragma unroll
        for (int pp = 0; pp < 2; pp++) {
            int col = pcol[pp];
            int d   = pd[pp];
            const float* gb = &gbuf[col * GBS];
            float ig = gb[d]            + ivr[pp][0] + bias_i[pp];
            float fg = gb[HID_ + d]     + ivr[pp][1] + bias_f[pp];
            float og = gb[2 * HID_ + d] + ivr[pp][2] + bias_o[pp];
            float gg = gb[3 * HID_ + d] + ivr[pp][3] + bias_g[pp];
            float cv = sigm_hw(fg) * creg[pp] + sigm_hw(ig) * tanh_hw(gg);
            float hv = sigm_hw(og) * tanh_hw(cv);
            creg[pp] = cv;
            hfp[d * HP + col] = hv;
            float hh, hl;
            split2(hv, hh, hl);
            hbh[col * HBS + d] = __float2bfloat16(hh);
            hbl[col * HBS + d] = __float2bfloat16(hl);
        }
        __syncthreads();

        if (t < HID_) {
            const int d = t;
            float4 v0 = make_float4(hfp[d * HP + 0], hfp[d * HP + 1],
                                    hfp[d * HP + 2], hfp[d * HP + 3]);
            float4 v1 = make_float4(hfp[d * HP + 4], hfp[d * HP + 5],
                                    hfp[d * HP + 6], hfp[d * HP + 7]);
            float* op = out + ((((size_t)b * HID_ + d) * H_) + row) * W_ + w0;
            *reinterpret_cast<float4*>(op)     = v0;
            *reinterpret_cast<float4*>(op + 4) = v1;
        }
        __syncthreads();
    }
}

// ---------------------------------------------------------------------------
extern "C" void kernel_launch(void* const* d_in, const int* in_sizes, int n_in,
                              void* d_out, int out_size)
{
    (void)in_sizes; (void)n_in; (void)out_size;
    const float* x  = (const float*)d_in[0];
    const float* Wi = (const float*)d_in[1];
    const float* bi = (const float*)d_in[2];
    const float* Wh = (const float*)d_in[3];
    const float* bh = (const float*)d_in[4];
    float* out = (float*)d_out;

    static bool attr_set = false;
    if (!attr_set) {
        cudaFuncSetAttribute(i2h_kernel, cudaFuncAttributeMaxDynamicSharedMemorySize, SMEM_I2H);
        attr_set = true;
    }

    prep_x<<<B_ * H_, 256>>>(x);
    prep_w<<<160, 512>>>(Wi, Wh);
    i2h_kernel<<<512, 256, SMEM_I2H>>>();
    rec_kernel<<<B_ * (W_ / 8), 512>>>(bi, bh, out);
}

// round 15
// speedup vs baseline: 1.2390x; 1.0989x over previous
#include <cuda_runtime.h>
#include <cuda_bf16.h>
#include <cuda_fp16.h>
#include <cstdint>

// ---------------------------------------------------------------------------
// RowLSTM: x(16,64,64,64), Wi(512,64,1,3), bi(512), Wh(512,128), bh(512)
// out: (16,128,64,64) fp32
// Phase 1 (i2h): mma.sync bf16 3-pass hi/lo conv-GEMM -> fp16 gate scratch
// Phase 2 (rec): 512-thr mma scan, register-resident Wh, HW tanh pointwise,
//                2 barriers/row.
// ---------------------------------------------------------------------------

#define B_  16
#define C_  64
#define H_  64
#define W_  64
#define HID_ 128
#define G_  512
#define K_  192

static __device__ __half   g_i2h[(size_t)H_ * B_ * W_ * G_];   // [h][b][w][g] fp16 (67 MB)
static __device__ uint32_t g_xTh[(size_t)B_ * H_ * 66 * 32];   // [b][h][wp][cq] bf16x2 hi
static __device__ uint32_t g_xTl[(size_t)B_ * H_ * 66 * 32];   // lo
static __device__ uint32_t g_WiFh[49152];                      // [kw][kt][mt][lane][reg]
static __device__ uint32_t g_WiFl[49152];
static __device__ uint32_t g_WhFh[32768];                      // [kt(8)][mt(32)][lane(32)][reg(4)]

__device__ __forceinline__ float tanh_hw(float v) {
    float r; asm("tanh.approx.f32 %0, %1;" : "=f"(r) : "f"(v)); return r;
}
__device__ __forceinline__ float sigm_hw(float v) {
    return fmaf(tanh_hw(0.5f * v), 0.5f, 0.5f);
}
__device__ __forceinline__ uint32_t pkbf(float a, float b) {
    __nv_bfloat162 t = __floats2bfloat162_rn(a, b);
    return *reinterpret_cast<uint32_t*>(&t);
}
__device__ __forceinline__ void split2(float v, float& hi, float& lo) {
    __nv_bfloat16 h = __float2bfloat16_rn(v);
    hi = __bfloat162float(h);
    lo = v - hi;
}
__device__ __forceinline__ void mma_bf16(float d[4], const uint32_t a[4], const uint32_t b[2]) {
    asm volatile(
        "mma.sync.aligned.m16n8k16.row.col.f32.bf16.bf16.f32 "
        "{%0,%1,%2,%3},{%4,%5,%6,%7},{%8,%9},{%0,%1,%2,%3};"
        : "+f"(d[0]), "+f"(d[1]), "+f"(d[2]), "+f"(d[3])
        : "r"(a[0]), "r"(a[1]), "r"(a[2]), "r"(a[3]), "r"(b[0]), "r"(b[1]));
}

// ---------------------------------------------------------------------------
// Prep 1: x -> xT hi/lo bf16x2, layout [b][h][wp(66)][cq(32)], zero-padded ends
// ---------------------------------------------------------------------------
__global__ void __launch_bounds__(256)
prep_x(const float* __restrict__ x)
{
    const int b = blockIdx.x >> 6, h = blockIdx.x & 63;
    const int tid = threadIdx.x;
    __shared__ float xt[64][65];
    for (int idx = tid; idx < 4096; idx += 256) {
        int c = idx >> 6, w = idx & 63;
        xt[c][w] = x[(((size_t)b * C_ + c) * H_ + h) * W_ + w];
    }
    __syncthreads();
    for (int idx = tid; idx < 66 * 32; idx += 256) {
        int wp = idx >> 5, cq = idx & 31, c0 = cq * 2;
        uint32_t vh = 0u, vl = 0u;
        if (wp >= 1 && wp <= 64) {
            int w = wp - 1;
            float ah, al, bh, bl;
            split2(xt[c0][w], ah, al);
            split2(xt[c0 + 1][w], bh, bl);
            vh = pkbf(ah, bh);
            vl = pkbf(al, bl);
        }
        size_t o = (((size_t)b * H_ + h) * 66 + wp) * 32 + cq;
        g_xTh[o] = vh;
        g_xTl[o] = vl;
    }
}

// ---------------------------------------------------------------------------
// Prep 2 (merged): Wi frags (blocks 0..95), Wh frags (blocks 96..159)
// ---------------------------------------------------------------------------
__global__ void __launch_bounds__(512)
prep_w(const float* __restrict__ Wi, const float* __restrict__ Wh)
{
    if (blockIdx.x < 96) {
        int gid = blockIdx.x * 512 + threadIdx.x;
        int reg = gid & 3, lane = (gid >> 2) & 31, mt = (gid >> 7) & 31;
        int kt = (gid >> 12) & 3, kw = gid >> 14;
        int grp = lane >> 2, tig = lane & 3;
        int g  = mt * 16 + grp + 8 * (reg & 1);
        int c0 = kt * 16 + 2 * tig + 8 * (reg >> 1);
        float a = Wi[(size_t)g * K_ + c0 * 3 + kw];
        float b = Wi[(size_t)g * K_ + (c0 + 1) * 3 + kw];
        float ah, al, bh, bl;
        split2(a, ah, al);
        split2(b, bh, bl);
        g_WiFh[gid] = pkbf(ah, bh);
        g_WiFl[gid] = pkbf(al, bl);
    } else {
        int gid = (blockIdx.x - 96) * 512 + threadIdx.x;
        int reg = gid & 3, lane = (gid >> 2) & 31, mt = (gid >> 7) & 31;
        int kt = gid >> 12;
        int grp = lane >> 2, tig = lane & 3;
        int g = mt * 16 + grp + 8 * (reg & 1);
        int k = kt * 16 + 2 * tig + 8 * (reg >> 1);
        float a = Wh[(size_t)g * HID_ + k];
        float b = Wh[(size_t)g * HID_ + k + 1];
        g_WhFh[gid] = pkbf(__bfloat162float(__float2bfloat16_rn(a)),
                           __bfloat162float(__float2bfloat16_rn(b)));
    }
}

// ---------------------------------------------------------------------------
// Kernel A: i2h. Grid 512 = gc(8) x b(16) x ic(4). 256 threads = 8 warps.
// ---------------------------------------------------------------------------
#define A_HI  0
#define A_LO  24576
#define XS_HI 49152
#define XS_LO 68160
#define STGB  49152
#define SMEM_I2H 87168

__global__ void __launch_bounds__(256, 2)
i2h_kernel()
{
    extern __shared__ char sm[];
    const int gc = blockIdx.x & 7;
    const int b  = (blockIdx.x >> 3) & 15;
    const int ic = blockIdx.x >> 7;
    const int tid  = threadIdx.x;
    const int lane = tid & 31;
    const int warp = tid >> 5;
    const int wg   = warp >> 2;
    const int wn   = warp & 3;
    const int grp  = lane >> 2;
    const int tig  = lane & 3;

    uint4* ah4 = reinterpret_cast<uint4*>(sm + A_HI);
    uint4* al4 = reinterpret_cast<uint4*>(sm + A_LO);
    const uint4* wfh4 = reinterpret_cast<const uint4*>(g_WiFh);
    const uint4* wfl4 = reinterpret_cast<const uint4*>(g_WiFl);

    for (int idx = tid; idx < 1536; idx += 256) {
        int ln = idx & 31, gt = (idx >> 5) & 3, kt = (idx >> 7) & 3, kw = idx >> 9;
        int src = ((kw * 4 + kt) * 32 + gc * 4 + gt) * 32 + ln;
        int dst = ((kw * 4 + kt) * 4 + gt) * 32 + ln;
        ah4[dst] = wfh4[src];
        al4[dst] = wfl4[src];
    }

    int nbase[4];
#pragma unroll
    for (int nt2 = 0; nt2 < 4; nt2++) {
        int n = (wn * 4 + nt2) * 8 + grp;
        int hs = n >> 6, w = n & 63;
        nbase[nt2] = hs * 9504 + w * 144;
    }

    uint32_t* xh = reinterpret_cast<uint32_t*>(sm + XS_HI);
    uint32_t* xl = reinterpret_cast<uint32_t*>(sm + XS_LO);
    float* stg = reinterpret_cast<float*>(sm + STGB);

    for (int i = 0; i < 8; i++) {
        const int it = ic * 8 + i;
        const int h0 = it * 2;
        __syncthreads();

        for (int idx = tid; idx < 2 * 66 * 32; idx += 256) {
            int hs = idx >> 11;
            int rem = idx - hs * 2112;
            int wp = rem >> 5, cq = rem & 31;
            size_t g = (((size_t)b * H_ + h0 + hs) * 66 + wp) * 32 + cq;
            int d = hs * 2376 + wp * 36 + cq;
            xh[d] = g_xTh[g];
            xl[d] = g_xTl[g];
        }
        __syncthreads();

        float d[2][4][4];
#pragma unroll
        for (int a = 0; a < 2; a++)
#pragma unroll
            for (int c = 0; c < 4; c++)
#pragma unroll
                for (int r = 0; r < 4; r++) d[a][c][r] = 0.f;

#pragma unroll
        for (int kk = 0; kk < 12; kk++) {
            const int kw = kk >> 2, kt = kk & 3;
            const int koff = kw * 144 + kt * 32 + tig * 4;

            uint4 ahf[2], alf[2];
#pragma unroll
            for (int gt2 = 0; gt2 < 2; gt2++) {
                int fo = (kk * 4 + wg * 2 + gt2) * 32 + lane;
                ahf[gt2] = ah4[fo];
                alf[gt2] = al4[fo];
            }
            uint32_t bhf[4][2], blf[4][2];
#pragma unroll
            for (int nt2 = 0; nt2 < 4; nt2++) {
                int off = nbase[nt2] + koff;
                bhf[nt2][0] = *reinterpret_cast<const uint32_t*>(sm + XS_HI + off);
                bhf[nt2][1] = *reinterpret_cast<const uint32_t*>(sm + XS_HI + off + 16);
                blf[nt2][0] = *reinterpret_cast<const uint32_t*>(sm + XS_LO + off);
                blf[nt2][1] = *reinterpret_cast<const uint32_t*>(sm + XS_LO + off + 16);
            }
#pragma unroll
            for (int gt2 = 0; gt2 < 2; gt2++)
#pragma unroll
                for (int nt2 = 0; nt2 < 4; nt2++)
                    mma_bf16(d[gt2][nt2], &ahf[gt2].x, bhf[nt2]);
#pragma unroll
            for (int gt2 = 0; gt2 < 2; gt2++)
#pragma unroll
                for (int nt2 = 0; nt2 < 4; nt2++)
                    mma_bf16(d[gt2][nt2], &ahf[gt2].x, blf[nt2]);
#pragma unroll
            for (int gt2 = 0; gt2 < 2; gt2++)
#pragma unroll
                for (int nt2 = 0; nt2 < 4; nt2++)
                    mma_bf16(d[gt2][nt2], &alf[gt2].x, bhf[nt2]);
        }
        __syncthreads();

#pragma unroll
        for (int gt2 = 0; gt2 < 2; gt2++) {
            int g0 = (wg * 2 + gt2) * 16 + grp;
#pragma unroll
            for (int nt2 = 0; nt2 < 4; nt2++) {
                int n0 = (wn * 4 + nt2) * 8 + 2 * tig;
                stg[n0 * 64 + g0]           = d[gt2][nt2][0];
                stg[(n0 + 1) * 64 + g0]     = d[gt2][nt2][1];
                stg[n0 * 64 + g0 + 8]       = d[gt2][nt2][2];
                stg[(n0 + 1) * 64 + g0 + 8] = d[gt2][nt2][3];
            }
        }
        __syncthreads();

        // coalesced fp16 STG: 4 halves (8B) per thread-step
#pragma unroll
        for (int u = 0; u < 8; u++) {
            int idx = tid + u * 256;
            int n = idx >> 4;
            int q4 = idx & 15;
            float4 v = *reinterpret_cast<const float4*>(&stg[n * 64 + q4 * 4]);
            __half2 p0 = __floats2half2_rn(v.x, v.y);
            __half2 p1 = __floats2half2_rn(v.z, v.w);
            size_t dst = ((size_t)(h0 + (n >> 6)) * B_ + b) * (W_ * G_)
                       + (size_t)(n & 63) * G_ + gc * 64 + q4 * 4;
            *reinterpret_cast<__half2*>(&g_i2h[dst])     = p0;
            *reinterpret_cast<__half2*>(&g_i2h[dst + 2]) = p1;
        }
    }
}

// ---------------------------------------------------------------------------
// Kernel B: recurrent scan (R11/R14 winner): 512 thr, register-resident Wh,
// HW tanh, fp16 gate loads, 2 barriers/row.
// ---------------------------------------------------------------------------
#define GBS 516
#define HBS 136
#define HP  10

__global__ void __launch_bounds__(512, 1)
rec_kernel(const float* __restrict__ bi, const float* __restrict__ bh,
           float* __restrict__ out)
{
    const int b  = blockIdx.x >> 3;
    const int w0 = (blockIdx.x & 7) * 8;
    const int t  = threadIdx.x;
    const int lane = t & 31;
    const int warp = t >> 5;        // 0..15
    const int grp  = lane >> 2;
    const int tig  = lane & 3;

    __shared__ __nv_bfloat16 hbh[8 * HBS];
    __shared__ __nv_bfloat16 hbl[8 * HBS];
    __shared__ float hfp[HID_ * HP];
    __shared__ float gbuf[8 * GBS];

    for (int p = t; p < 8 * HBS; p += 512) {
        hbh[p] = __float2bfloat16(0.f);
        hbl[p] = __float2bfloat16(0.f);
    }
    __syncthreads();

    float bias_i[2], bias_f[2], bias_o[2], bias_g[2];
#pragma unroll
    for (int pp = 0; pp < 2; pp++) {
        int d = (t + pp * 512) & 127;
        bias_i[pp] = bi[d] + bh[d];
        bias_f[pp] = bi[HID_ + d] + bh[HID_ + d];
        bias_o[pp] = bi[2 * HID_ + d] + bh[2 * HID_ + d];
        bias_g[pp] = bi[3 * HID_ + d] + bh[3 * HID_ + d];
    }
    float creg[2] = {0.f, 0.f};

    const uint4* whfh = reinterpret_cast<const uint4*>(g_WhFh);
    const int mt0 = warp * 2;
    uint4 whr[16];
#pragma unroll
    for (int kt = 0; kt < 8; kt++) {
        whr[2 * kt]     = whfh[(kt * 32 + mt0) * 32 + lane];
        whr[2 * kt + 1] = whfh[(kt * 32 + mt0 + 1) * 32 + lane];
    }

    const int bofs = grp * (HBS * 2) + tig * 4;

    int pcol[2], pd[2];
#pragma unroll
    for (int pp = 0; pp < 2; pp++) {
        int p = t + pp * 512;
        pcol[pp] = p >> 7;
        pd[pp]   = p & 127;
    }

    for (int row = 0; row < H_; row++) {
        float ivr[2][4];
#pragma unroll
        for (int pp = 0; pp < 2; pp++) {
            const __half* iv = &g_i2h[((((size_t)row * B_ + b) * W_) + w0 + pcol[pp]) * G_ + pd[pp]];
            ivr[pp][0] = __half2float(__ldg(iv));
            ivr[pp][1] = __half2float(__ldg(iv + HID_));
            ivr[pp][2] = __half2float(__ldg(iv + 2 * HID_));
            ivr[pp][3] = __half2float(__ldg(iv + 3 * HID_));
        }

        float d0[4] = {0.f, 0.f, 0.f, 0.f};
        float d1[4] = {0.f, 0.f, 0.f, 0.f};
#pragma unroll
        for (int kt = 0; kt < 8; kt++) {
            uint32_t bhf[2], blf[2];
            const char* ph = reinterpret_cast<const char*>(hbh) + bofs + kt * 32;
            const char* pl = reinterpret_cast<const char*>(hbl) + bofs + kt * 32;
            bhf[0] = *reinterpret_cast<const uint32_t*>(ph);
            bhf[1] = *reinterpret_cast<const uint32_t*>(ph + 16);
            blf[0] = *reinterpret_cast<const uint32_t*>(pl);
            blf[1] = *reinterpret_cast<const uint32_t*>(pl + 16);
            mma_bf16(d0, &whr[2 * kt].x, bhf);
            mma_bf16(d1, &whr[2 * kt + 1].x, bhf);
            mma_bf16(d0, &whr[2 * kt].x, blf);
            mma_bf16(d1, &whr[2 * kt + 1].x, blf);
        }

        {
            int g0 = mt0 * 16 + grp;
            gbuf[(2 * tig) * GBS + g0]          = d0[0];
            gbuf[(2 * tig + 1) * GBS + g0]      = d0[1];
            gbuf[(2 * tig) * GBS + g0 + 8]      = d0[2];
            gbuf[(2 * tig + 1) * GBS + g0 + 8]  = d0[3];
            int g1 = g0 + 16;
            gbuf[(2 * tig) * GBS + g1]          = d1[0];
            gbuf[(2 * tig + 1) * GBS + g1]      = d1[1];
            gbuf[(2 * tig) * GBS + g1 + 8]      = d1[2];
            gbuf[(2 * tig + 1) * GBS + g1 + 8]  = d1[3];
        }
        __syncthreads();

#pragma unroll
        for (int pp = 0; pp < 2; pp++) {
            int col = pcol[pp];
            int d   = pd[pp];
            const float* gb = &gbuf[col * GBS];
            float ig = gb[d]            + ivr[pp][0] + bias_i[pp];
            float fg = gb[HID_ + d]     + ivr[pp][1] + bias_f[pp];
            float og = gb[2 * HID_ + d] + ivr[pp][2] + bias_o[pp];
            float gg = gb[3 * HID_ + d] + ivr[pp][3] + bias_g[pp];
            float cv = sigm_hw(fg) * creg[pp] + sigm_hw(ig) * tanh_hw(gg);
            float hv = sigm_hw(og) * tanh_hw(cv);
            creg[pp] = cv;
            hfp[d * HP + col] = hv;
            float hh, hl;
            split2(hv, hh, hl);
            hbh[col * HBS + d] = __float2bfloat16(hh);
            hbl[col * HBS + d] = __float2bfloat16(hl);
        }
        __syncthreads();

        if (t < HID_) {
            const int d = t;
            float4 v0 = make_float4(hfp[d * HP + 0], hfp[d * HP + 1],
                                    hfp[d * HP + 2], hfp[d * HP + 3]);
            float4 v1 = make_float4(hfp[d * HP + 4], hfp[d * HP + 5],
                                    hfp[d * HP + 6], hfp[d * HP + 7]);
            float* op = out + ((((size_t)b * HID_ + d) * H_) + row) * W_ + w0;
            *reinterpret_cast<float4*>(op)     = v0;
            *reinterpret_cast<float4*>(op + 4) = v1;
        }
        // no trailing barrier: next iteration's post-gbuf __syncthreads
        // already orders hfp/gbuf reuse against this out-write.
    }
}

// ---------------------------------------------------------------------------
extern "C" void kernel_launch(void* const* d_in, const int* in_sizes, int n_in,
                              void* d_out, int out_size)
{
    (void)in_sizes; (void)n_in; (void)out_size;
    const float* x  = (const float*)d_in[0];
    const float* Wi = (const float*)d_in[1];
    const float* bi = (const float*)d_in[2];
    const float* Wh = (const float*)d_in[3];
    const float* bh = (const float*)d_in[4];
    float* out = (float*)d_out;

    static bool attr_set = false;
    if (!attr_set) {
        cudaFuncSetAttribute(i2h_kernel, cudaFuncAttributeMaxDynamicSharedMemorySize, SMEM_I2H);
        attr_set = true;
    }

    prep_x<<<B_ * H_, 256>>>(x);
    prep_w<<<160, 512>>>(Wi, Wh);
    i2h_kernel<<<512, 256, SMEM_I2H>>>();
    rec_kernel<<<B_ * (W_ / 8), 512>>>(bi, bh, out);
}

// round 16
// speedup vs baseline: 1.3305x; 1.0738x over previous
#include <cuda_runtime.h>
#include <cuda_bf16.h>
#include <cuda_fp16.h>
#include <cstdint>

// ---------------------------------------------------------------------------
// RowLSTM: x(16,64,64,64), Wi(512,64,1,3), bi(512), Wh(512,128), bh(512)
// out: (16,128,64,64) fp32
// Phase 1 (i2h): mma.sync bf16 3-pass hi/lo conv-GEMM -> fp16 gate scratch
// Phase 2 (rec): 512-thr mma scan, register-resident Wh (bf16-hi), h in plain
//   bf16 (single pass), HW tanh pointwise, 2 barriers/row.
// ---------------------------------------------------------------------------

#define B_  16
#define C_  64
#define H_  64
#define W_  64
#define HID_ 128
#define G_  512
#define K_  192

static __device__ __half   g_i2h[(size_t)H_ * B_ * W_ * G_];   // [h][b][w][g] fp16 (67 MB)
static __device__ uint32_t g_xTh[(size_t)B_ * H_ * 66 * 32];   // [b][h][wp][cq] bf16x2 hi
static __device__ uint32_t g_xTl[(size_t)B_ * H_ * 66 * 32];   // lo
static __device__ uint32_t g_WiFh[49152];                      // [kw][kt][mt][lane][reg]
static __device__ uint32_t g_WiFl[49152];
static __device__ uint32_t g_WhFh[32768];                      // [kt(8)][mt(32)][lane(32)][reg(4)]

__device__ __forceinline__ float tanh_hw(float v) {
    float r; asm("tanh.approx.f32 %0, %1;" : "=f"(r) : "f"(v)); return r;
}
__device__ __forceinline__ float sigm_hw(float v) {
    return fmaf(tanh_hw(0.5f * v), 0.5f, 0.5f);
}
__device__ __forceinline__ uint32_t pkbf(float a, float b) {
    __nv_bfloat162 t = __floats2bfloat162_rn(a, b);
    return *reinterpret_cast<uint32_t*>(&t);
}
__device__ __forceinline__ void split2(float v, float& hi, float& lo) {
    __nv_bfloat16 h = __float2bfloat16_rn(v);
    hi = __bfloat162float(h);
    lo = v - hi;
}
__device__ __forceinline__ void mma_bf16(float d[4], const uint32_t a[4], const uint32_t b[2]) {
    asm volatile(
        "mma.sync.aligned.m16n8k16.row.col.f32.bf16.bf16.f32 "
        "{%0,%1,%2,%3},{%4,%5,%6,%7},{%8,%9},{%0,%1,%2,%3};"
        : "+f"(d[0]), "+f"(d[1]), "+f"(d[2]), "+f"(d[3])
        : "r"(a[0]), "r"(a[1]), "r"(a[2]), "r"(a[3]), "r"(b[0]), "r"(b[1]));
}

// ---------------------------------------------------------------------------
// Prep 1: x -> xT hi/lo bf16x2, layout [b][h][wp(66)][cq(32)], zero-padded ends
// ---------------------------------------------------------------------------
__global__ void __launch_bounds__(256)
prep_x(const float* __restrict__ x)
{
    const int b = blockIdx.x >> 6, h = blockIdx.x & 63;
    const int tid = threadIdx.x;
    __shared__ float xt[64][65];
    for (int idx = tid; idx < 4096; idx += 256) {
        int c = idx >> 6, w = idx & 63;
        xt[c][w] = x[(((size_t)b * C_ + c) * H_ + h) * W_ + w];
    }
    __syncthreads();
    for (int idx = tid; idx < 66 * 32; idx += 256) {
        int wp = idx >> 5, cq = idx & 31, c0 = cq * 2;
        uint32_t vh = 0u, vl = 0u;
        if (wp >= 1 && wp <= 64) {
            int w = wp - 1;
            float ah, al, bh, bl;
            split2(xt[c0][w], ah, al);
            split2(xt[c0 + 1][w], bh, bl);
            vh = pkbf(ah, bh);
            vl = pkbf(al, bl);
        }
        size_t o = (((size_t)b * H_ + h) * 66 + wp) * 32 + cq;
        g_xTh[o] = vh;
        g_xTl[o] = vl;
    }
}

// ---------------------------------------------------------------------------
// Prep 2 (merged): Wi frags (blocks 0..95), Wh frags (blocks 96..159)
// ---------------------------------------------------------------------------
__global__ void __launch_bounds__(512)
prep_w(const float* __restrict__ Wi, const float* __restrict__ Wh)
{
    if (blockIdx.x < 96) {
        int gid = blockIdx.x * 512 + threadIdx.x;
        int reg = gid & 3, lane = (gid >> 2) & 31, mt = (gid >> 7) & 31;
        int kt = (gid >> 12) & 3, kw = gid >> 14;
        int grp = lane >> 2, tig = lane & 3;
        int g  = mt * 16 + grp + 8 * (reg & 1);
        int c0 = kt * 16 + 2 * tig + 8 * (reg >> 1);
        float a = Wi[(size_t)g * K_ + c0 * 3 + kw];
        float b = Wi[(size_t)g * K_ + (c0 + 1) * 3 + kw];
        float ah, al, bh, bl;
        split2(a, ah, al);
        split2(b, bh, bl);
        g_WiFh[gid] = pkbf(ah, bh);
        g_WiFl[gid] = pkbf(al, bl);
    } else {
        int gid = (blockIdx.x - 96) * 512 + threadIdx.x;
        int reg = gid & 3, lane = (gid >> 2) & 31, mt = (gid >> 7) & 31;
        int kt = gid >> 12;
        int grp = lane >> 2, tig = lane & 3;
        int g = mt * 16 + grp + 8 * (reg & 1);
        int k = kt * 16 + 2 * tig + 8 * (reg >> 1);
        float a = Wh[(size_t)g * HID_ + k];
        float b = Wh[(size_t)g * HID_ + k + 1];
        g_WhFh[gid] = pkbf(__bfloat162float(__float2bfloat16_rn(a)),
                           __bfloat162float(__float2bfloat16_rn(b)));
    }
}

// ---------------------------------------------------------------------------
// Kernel A: i2h. Grid 512 = gc(8) x b(16) x ic(4). 256 threads = 8 warps.
// ---------------------------------------------------------------------------
#define A_HI  0
#define A_LO  24576
#define XS_HI 49152
#define XS_LO 68160
#define STGB  49152
#define SMEM_I2H 87168

__global__ void __launch_bounds__(256, 2)
i2h_kernel()
{
    extern __shared__ char sm[];
    const int gc = blockIdx.x & 7;
    const int b  = (blockIdx.x >> 3) & 15;
    const int ic = blockIdx.x >> 7;
    const int tid  = threadIdx.x;
    const int lane = tid & 31;
    const int warp = tid >> 5;
    const int wg   = warp >> 2;
    const int wn   = warp & 3;
    const int grp  = lane >> 2;
    const int tig  = lane & 3;

    uint4* ah4 = reinterpret_cast<uint4*>(sm + A_HI);
    uint4* al4 = reinterpret_cast<uint4*>(sm + A_LO);
    const uint4* wfh4 = reinterpret_cast<const uint4*>(g_WiFh);
    const uint4* wfl4 = reinterpret_cast<const uint4*>(g_WiFl);

    for (int idx = tid; idx < 1536; idx += 256) {
        int ln = idx & 31, gt = (idx >> 5) & 3, kt = (idx >> 7) & 3, kw = idx >> 9;
        int src = ((kw * 4 + kt) * 32 + gc * 4 + gt) * 32 + ln;
        int dst = ((kw * 4 + kt) * 4 + gt) * 32 + ln;
        ah4[dst] = wfh4[src];
        al4[dst] = wfl4[src];
    }

    int nbase[4];
#pragma unroll
    for (int nt2 = 0; nt2 < 4; nt2++) {
        int n = (wn * 4 + nt2) * 8 + grp;
        int hs = n >> 6, w = n & 63;
        nbase[nt2] = hs * 9504 + w * 144;
    }

    uint32_t* xh = reinterpret_cast<uint32_t*>(sm + XS_HI);
    uint32_t* xl = reinterpret_cast<uint32_t*>(sm + XS_LO);
    float* stg = reinterpret_cast<float*>(sm + STGB);

    for (int i = 0; i < 8; i++) {
        const int it = ic * 8 + i;
        const int h0 = it * 2;
        __syncthreads();

        for (int idx = tid; idx < 2 * 66 * 32; idx += 256) {
            int hs = idx >> 11;
            int rem = idx - hs * 2112;
            int wp = rem >> 5, cq = rem & 31;
            size_t g = (((size_t)b * H_ + h0 + hs) * 66 + wp) * 32 + cq;
            int d = hs * 2376 + wp * 36 + cq;
            xh[d] = g_xTh[g];
            xl[d] = g_xTl[g];
        }
        __syncthreads();

        float d[2][4][4];
#pragma unroll
        for (int a = 0; a < 2; a++)
#pragma unroll
            for (int c = 0; c < 4; c++)
#pragma unroll
                for (int r = 0; r < 4; r++) d[a][c][r] = 0.f;

#pragma unroll
        for (int kk = 0; kk < 12; kk++) {
            const int kw = kk >> 2, kt = kk & 3;
            const int koff = kw * 144 + kt * 32 + tig * 4;

            uint4 ahf[2], alf[2];
#pragma unroll
            for (int gt2 = 0; gt2 < 2; gt2++) {
                int fo = (kk * 4 + wg * 2 + gt2) * 32 + lane;
                ahf[gt2] = ah4[fo];
                alf[gt2] = al4[fo];
            }
            uint32_t bhf[4][2], blf[4][2];
#pragma unroll
            for (int nt2 = 0; nt2 < 4; nt2++) {
                int off = nbase[nt2] + koff;
                bhf[nt2][0] = *reinterpret_cast<const uint32_t*>(sm + XS_HI + off);
                bhf[nt2][1] = *reinterpret_cast<const uint32_t*>(sm + XS_HI + off + 16);
                blf[nt2][0] = *reinterpret_cast<const uint32_t*>(sm + XS_LO + off);
                blf[nt2][1] = *reinterpret_cast<const uint32_t*>(sm + XS_LO + off + 16);
            }
#pragma unroll
            for (int gt2 = 0; gt2 < 2; gt2++)
#pragma unroll
                for (int nt2 = 0; nt2 < 4; nt2++)
                    mma_bf16(d[gt2][nt2], &ahf[gt2].x, bhf[nt2]);
#pragma unroll
            for (int gt2 = 0; gt2 < 2; gt2++)
#pragma unroll
                for (int nt2 = 0; nt2 < 4; nt2++)
                    mma_bf16(d[gt2][nt2], &ahf[gt2].x, blf[nt2]);
#pragma unroll
            for (int gt2 = 0; gt2 < 2; gt2++)
#pragma unroll
                for (int nt2 = 0; nt2 < 4; nt2++)
                    mma_bf16(d[gt2][nt2], &alf[gt2].x, bhf[nt2]);
        }
        __syncthreads();

#pragma unroll
        for (int gt2 = 0; gt2 < 2; gt2++) {
            int g0 = (wg * 2 + gt2) * 16 + grp;
#pragma unroll
            for (int nt2 = 0; nt2 < 4; nt2++) {
                int n0 = (wn * 4 + nt2) * 8 + 2 * tig;
                stg[n0 * 64 + g0]           = d[gt2][nt2][0];
                stg[(n0 + 1) * 64 + g0]     = d[gt2][nt2][1];
                stg[n0 * 64 + g0 + 8]       = d[gt2][nt2][2];
                stg[(n0 + 1) * 64 + g0 + 8] = d[gt2][nt2][3];
            }
        }
        __syncthreads();

#pragma unroll
        for (int u = 0; u < 8; u++) {
            int idx = tid + u * 256;
            int n = idx >> 4;
            int q4 = idx & 15;
            float4 v = *reinterpret_cast<const float4*>(&stg[n * 64 + q4 * 4]);
            __half2 p0 = __floats2half2_rn(v.x, v.y);
            __half2 p1 = __floats2half2_rn(v.z, v.w);
            size_t dst = ((size_t)(h0 + (n >> 6)) * B_ + b) * (W_ * G_)
                       + (size_t)(n & 63) * G_ + gc * 64 + q4 * 4;
            *reinterpret_cast<__half2*>(&g_i2h[dst])     = p0;
            *reinterpret_cast<__half2*>(&g_i2h[dst + 2]) = p1;
        }
    }
}

// ---------------------------------------------------------------------------
// Kernel B: recurrent scan: 512 thr, register-resident Wh-hi, h plain bf16
// (single-pass), HW tanh, fp16 gate loads, 2 barriers/row.
// ---------------------------------------------------------------------------
#define GBS 516
#define HBS 136
#define HP  10

__global__ void __launch_bounds__(512, 1)
rec_kernel(const float* __restrict__ bi, const float* __restrict__ bh,
           float* __restrict__ out)
{
    const int b  = blockIdx.x >> 3;
    const int w0 = (blockIdx.x & 7) * 8;
    const int t  = threadIdx.x;
    const int lane = t & 31;
    const int warp = t >> 5;        // 0..15
    const int grp  = lane >> 2;
    const int tig  = lane & 3;

    __shared__ __nv_bfloat16 hbh[8 * HBS];
    __shared__ float hfp[HID_ * HP];
    __shared__ float gbuf[8 * GBS];

    for (int p = t; p < 8 * HBS; p += 512) hbh[p] = __float2bfloat16(0.f);
    __syncthreads();

    float bias_i[2], bias_f[2], bias_o[2], bias_g[2];
#pragma unroll
    for (int pp = 0; pp < 2; pp++) {
        int d = (t + pp * 512) & 127;
        bias_i[pp] = bi[d] + bh[d];
        bias_f[pp] = bi[HID_ + d] + bh[HID_ + d];
        bias_o[pp] = bi[2 * HID_ + d] + bh[2 * HID_ + d];
        bias_g[pp] = bi[3 * HID_ + d] + bh[3 * HID_ + d];
    }
    float creg[2] = {0.f, 0.f};

    const uint4* whfh = reinterpret_cast<const uint4*>(g_WhFh);
    const int mt0 = warp * 2;
    uint4 whr[16];
#pragma unroll
    for (int kt = 0; kt < 8; kt++) {
        whr[2 * kt]     = whfh[(kt * 32 + mt0) * 32 + lane];
        whr[2 * kt + 1] = whfh[(kt * 32 + mt0 + 1) * 32 + lane];
    }

    const int bofs = grp * (HBS * 2) + tig * 4;

    int pcol[2], pd[2];
#pragma unroll
    for (int pp = 0; pp < 2; pp++) {
        int p = t + pp * 512;
        pcol[pp] = p >> 7;
        pd[pp]   = p & 127;
    }

    for (int row = 0; row < H_; row++) {
        float ivr[2][4];
#pragma unroll
        for (int pp = 0; pp < 2; pp++) {
            const __half* iv = &g_i2h[((((size_t)row * B_ + b) * W_) + w0 + pcol[pp]) * G_ + pd[pp]];
            ivr[pp][0] = __half2float(__ldg(iv));
            ivr[pp][1] = __half2float(__ldg(iv + HID_));
            ivr[pp][2] = __half2float(__ldg(iv + 2 * HID_));
            ivr[pp][3] = __half2float(__ldg(iv + 3 * HID_));
        }

        float d0[4] = {0.f, 0.f, 0.f, 0.f};
        float d1[4] = {0.f, 0.f, 0.f, 0.f};
#pragma unroll
        for (int kt = 0; kt < 8; kt++) {
            uint32_t bhf[2];
            const char* ph = reinterpret_cast<const char*>(hbh) + bofs + kt * 32;
            bhf[0] = *reinterpret_cast<const uint32_t*>(ph);
            bhf[1] = *reinterpret_cast<const uint32_t*>(ph + 16);
            mma_bf16(d0, &whr[2 * kt].x, bhf);
            mma_bf16(d1, &whr[2 * kt + 1].x, bhf);
        }

        {
            int g0 = mt0 * 16 + grp;
            gbuf[(2 * tig) * GBS + g0]          = d0[0];
            gbuf[(2 * tig + 1) * GBS + g0]      = d0[1];
            gbuf[(2 * tig) * GBS + g0 + 8]      = d0[2];
            gbuf[(2 * tig + 1) * GBS + g0 + 8]  = d0[3];
            int g1 = g0 + 16;
            gbuf[(2 * tig) * GBS + g1]          = d1[0];
            gbuf[(2 * tig + 1) * GBS + g1]      = d1[1];
            gbuf[(2 * tig) * GBS + g1 + 8]      = d1[2];
            gbuf[(2 * tig + 1) * GBS + g1 + 8]  = d1[3];
        }
        __syncthreads();

#pragma unroll
        for (int pp = 0; pp < 2; pp++) {
            int col = pcol[pp];
            int d   = pd[pp];
            const float* gb = &gbuf[col * GBS];
            float ig = gb[d]            + ivr[pp][0] + bias_i[pp];
            float fg = gb[HID_ + d]     + ivr[pp][1] + bias_f[pp];
            float og = gb[2 * HID_ + d] + ivr[pp][2] + bias_o[pp];
            float gg = gb[3 * HID_ + d] + ivr[pp][3] + bias_g[pp];
            float cv = sigm_hw(fg) * creg[pp] + sigm_hw(ig) * tanh_hw(gg);
            float hv = sigm_hw(og) * tanh_hw(cv);
            creg[pp] = cv;
            hfp[d * HP + col] = hv;
            hbh[col * HBS + d] = __float2bfloat16_rn(hv);
        }
        __syncthreads();

        if (t < HID_) {
            const int d = t;
            float4 v0 = make_float4(hfp[d * HP + 0], hfp[d * HP + 1],
                                    hfp[d * HP + 2], hfp[d * HP + 3]);
            float4 v1 = make_float4(hfp[d * HP + 4], hfp[d * HP + 5],
                                    hfp[d * HP + 6], hfp[d * HP + 7]);
            float* op = out + ((((size_t)b * HID_ + d) * H_) + row) * W_ + w0;
            *reinterpret_cast<float4*>(op)     = v0;
            *reinterpret_cast<float4*>(op + 4) = v1;
        }
        // no trailing barrier: next iteration's post-gbuf __syncthreads
        // already orders hfp/gbuf/hbh reuse against this out-write.
    }
}

// ---------------------------------------------------------------------------
extern "C" void kernel_launch(void* const* d_in, const int* in_sizes, int n_in,
                              void* d_out, int out_size)
{
    (void)in_sizes; (void)n_in; (void)out_size;
    const float* x  = (const float*)d_in[0];
    const float* Wi = (const float*)d_in[1];
    const float* bi = (const float*)d_in[2];
    const float* Wh = (const float*)d_in[3];
    const float* bh = (const float*)d_in[4];
    float* out = (float*)d_out;

    static bool attr_set = false;
    if (!attr_set) {
        cudaFuncSetAttribute(i2h_kernel, cudaFuncAttributeMaxDynamicSharedMemorySize, SMEM_I2H);
        attr_set = true;
    }

    prep_x<<<B_ * H_, 256>>>(x);
    prep_w<<<160, 512>>>(Wi, Wh);
    i2h_kernel<<<512, 256, SMEM_I2H>>>();
    rec_kernel<<<B_ * (W_ / 8), 512>>>(bi, bh, out);
}